// round 13
// baseline (speedup 1.0000x reference)
#include <cuda_runtime.h>
#include <cuda_bf16.h>
#include <float.h>

#define NN 100000
#define NE 1600000
#define DIM 32
#define NEG_SLOPE 0.2f
#define CSR_BLOCKS 148
#define CSR_THREADS 1024

// -------- static device scratch (16B aligned for float4 access) --------
// Invariant: g_deg == 0 at every kernel_launch entry (zero at module load,
// re-zeroed by k_attn each call). Barrier cnt returns to 0 after each use;
// gen increases monotonically (wrap-safe).
__device__ int      g_deg[NN];
__device__ int      g_cursor[NN];
__device__ int      g_rowptr[NN + 1];
__device__ int      g_partial[CSR_BLOCKS];
__device__ unsigned g_bar_cnt = 0;
__device__ unsigned g_bar_gen = 0;
__device__ int      g_csrc[NE];                    // src ids grouped by dst (CSR)
__device__ float    g_Dinv[NN];
__device__ __align__(16) float g_A[NN * DIM];      // pass-1 agg input (u*Dinv)
__device__ __align__(16) float g_A2[NN * DIM];     // pass-2 agg input (X1*Dinv)
__device__ __align__(16) float g_X1[NN * DIM];
__device__ __align__(16) float g_FS[NN * DIM];     // fsrc
__device__ __align__(16) float g_FD[NN * DIM];     // fdst

// Sense-reversing grid barrier. Safe: all CSR_BLOCKS are co-resident
// (1 block/SM, 148 <= 152 SMs on GB300).
__device__ __forceinline__ void grid_bar() {
    __syncthreads();
    if (threadIdx.x == 0) {
        __threadfence();
        unsigned gen = *(volatile unsigned*)&g_bar_gen;
        unsigned a = atomicAdd(&g_bar_cnt, 1u);
        if (a == gridDim.x - 1) {
            *(volatile unsigned*)&g_bar_cnt = 0;
            __threadfence();
            atomicAdd(&g_bar_gen, 1u);            // release
        } else {
            while (*(volatile unsigned*)&g_bar_gen == gen) __nanosleep(64);
        }
        __threadfence();
    }
    __syncthreads();
}

// Block-wide exclusive scan over 1024 threads. Returns (exclusive, total).
// Uses caller-provided 32-int smem; safe for reuse after return.
__device__ __forceinline__ int2 block_scan(int v, int* swarp) {
    int lane = threadIdx.x & 31, w5 = threadIdx.x >> 5;
    int x = v;
#pragma unroll
    for (int off = 1; off < 32; off <<= 1) {
        int y = __shfl_up_sync(0xffffffffu, x, off);
        if (lane >= off) x += y;
    }
    if (lane == 31) swarp[w5] = x;
    __syncthreads();
    if (w5 == 0) {
        int s = swarp[lane];
#pragma unroll
        for (int off = 1; off < 32; off <<= 1) {
            int y = __shfl_up_sync(0xffffffffu, s, off);
            if (lane >= off) s += y;
        }
        swarp[lane] = s;
    }
    __syncthreads();
    int incl = x + (w5 > 0 ? swarp[w5 - 1] : 0);
    int total = swarp[31];
    __syncthreads();                               // protect smem reuse
    return make_int2(incl - v, total);
}

// Fused CSR build: hist -> scan -> (Dinv, rowptr, cursor, A=u*Dinv) -> scatter.
// One persistent kernel, 4 grid barriers. No thread returns before the end.
__global__ __launch_bounds__(CSR_THREADS, 1)
void k_csr(const float* __restrict__ u, const int* __restrict__ esrc,
           const int* __restrict__ edst, int n, int e) {
    __shared__ int swarp[32];
    int tid = threadIdx.x, bid = blockIdx.x;
    int gt = bid * CSR_THREADS + tid;
    int gsz = gridDim.x * CSR_THREADS;

    // ---- phase A: degree histogram ----
    for (int i = gt; i < e; i += gsz)
        atomicAdd(&g_deg[edst[i]], 1);
    grid_bar();

    // ---- phase B1: block-local scan of degrees (1 node / thread) ----
    int node = gt;                                  // block b owns nodes [b*1024, ...)
    int v = (node < n) ? g_deg[node] : 0;
    int2 sc = block_scan(v, swarp);
    if (tid == 0) g_partial[bid] = sc.y;
    grid_bar();

    // ---- phase B2: block 0 scans the 148 block totals ----
    if (bid == 0) {
        int vv = (tid < CSR_BLOCKS) ? g_partial[tid] : 0;
        int2 sc2 = block_scan(vv, swarp);
        if (tid < CSR_BLOCKS) g_partial[tid] = sc2.x;
        if (tid == CSR_BLOCKS - 1) g_rowptr[n] = sc2.x + vv;   // grand total
    }
    grid_bar();

    // ---- phase B3: write rowptr / cursor / Dinv ----
    if (node < n) {
        int off = g_partial[bid] + sc.x;
        g_rowptr[node] = off;
        g_cursor[node] = off;
        float dg = (float)v;
        g_Dinv[node] = rsqrtf(dg < 1.0f ? 1.0f : dg);
    }
    grid_bar();

    // ---- phase C: A = u * Dinv (float4) + scatter edges into CSR ----
    const float4* u4 = (const float4*)u;
    float4* A4 = (float4*)g_A;
    int n8 = n * 8;
    for (int j = gt; j < n8; j += gsz) {
        float d = g_Dinv[j >> 3];
        float4 vv = u4[j];
        vv.x *= d; vv.y *= d; vv.z *= d; vv.w *= d;
        A4[j] = vv;
    }
    for (int i = gt; i < e; i += gsz) {
        int p = atomicAdd(&g_cursor[edst[i]], 1);
        g_csrc[p] = esrc[i];
    }
}

// agg pass 1 fused with cheb1. Warp per node; 4 groups of 8 lanes, group =
// edge. Plain counted loop — measured fastest (R8/R12: ~33us).
__global__ void k_aggcheb(const float* __restrict__ u, const float* __restrict__ lam, int n) {
    int w = (blockIdx.x * blockDim.x + threadIdx.x) >> 5;
    int lane = threadIdx.x & 31;
    if (w >= n) return;
    int grp = lane >> 3, sub = lane & 7;
    int s0 = g_rowptr[w], s1 = g_rowptr[w + 1];
    const float4* A4 = (const float4*)g_A;
    float4 acc = make_float4(0.f, 0.f, 0.f, 0.f);
    for (int e = s0 + grp; e < s1; e += 4) {
        int sid = g_csrc[e];
        float4 v = A4[sid * 8 + sub];
        acc.x += v.x; acc.y += v.y; acc.z += v.z; acc.w += v.w;
    }
    // all lanes reconverged: full-warp shuffles safe
#pragma unroll
    for (int off = 8; off <= 16; off <<= 1) {
        acc.x += __shfl_xor_sync(0xffffffffu, acc.x, off);
        acc.y += __shfl_xor_sync(0xffffffffu, acc.y, off);
        acc.z += __shfl_xor_sync(0xffffffffu, acc.z, off);
        acc.w += __shfl_xor_sync(0xffffffffu, acc.w, off);
    }
    if (grp == 0) {
        float d = g_Dinv[w];
        float r = 2.0f / lam[0];
        float4 uv = ((const float4*)u)[w * 8 + sub];
        float4 x1;
        x1.x = -r * (acc.x * d) + (r - 1.0f) * uv.x;
        x1.y = -r * (acc.y * d) + (r - 1.0f) * uv.y;
        x1.z = -r * (acc.z * d) + (r - 1.0f) * uv.z;
        x1.w = -r * (acc.w * d) + (r - 1.0f) * uv.w;
        ((float4*)g_X1)[w * 8 + sub] = x1;
        float4 a; a.x = x1.x * d; a.y = x1.y * d; a.z = x1.z * d; a.w = x1.w * d;
        ((float4*)g_A2)[w * 8 + sub] = a;
    }
}

// agg pass 2 fused with node GEMMs. 1024-thread blocks = 32 nodes/block.
__global__ __launch_bounds__(1024, 1)
void k_aggnode(const float* __restrict__ u, const float* __restrict__ lam,
               const float* __restrict__ Wc, const float* __restrict__ bc,
               const float* __restrict__ Ws, const float* __restrict__ bs,
               const float* __restrict__ Wd, const float* __restrict__ bd,
               int n) {
    __shared__ __align__(16) float sW1t[32 * 100];
    __shared__ __align__(16) float sW2t[32 * 36];
    __shared__ __align__(16) float sW3t[32 * 36];
    __shared__ float sb1[32], sb2[32], sb3[32];
    __shared__ __align__(16) float xsh[32][96];
    __shared__ __align__(16) float hcsh[32][32];

    int tid = threadIdx.x;
    for (int i = tid; i < 96 * 32; i += 1024) {
        int j = i >> 5, d = i & 31;
        sW1t[d * 100 + j] = Wc[i];
    }
    for (int i = tid; i < 32 * 32; i += 1024) {
        int j = i >> 5, d = i & 31;
        sW2t[d * 36 + j] = Ws[i];
        sW3t[d * 36 + j] = Wd[i];
    }
    if (tid < 32) { sb1[tid] = bc[tid]; sb2[tid] = bs[tid]; sb3[tid] = bd[tid]; }
    __syncthreads();

    int wid = tid >> 5, lane = tid & 31;
    int node = blockIdx.x * 32 + wid;
    if (node >= n) return;
    int grp = lane >> 3, sub = lane & 7;

    int s0 = g_rowptr[node], s1 = g_rowptr[node + 1];
    const float4* A4 = (const float4*)g_A2;
    float4 acc = make_float4(0.f, 0.f, 0.f, 0.f);
    for (int e = s0 + grp; e < s1; e += 4) {
        int sid = g_csrc[e];
        float4 v = A4[sid * 8 + sub];
        acc.x += v.x; acc.y += v.y; acc.z += v.z; acc.w += v.w;
    }
#pragma unroll
    for (int off = 8; off <= 16; off <<= 1) {
        acc.x += __shfl_xor_sync(0xffffffffu, acc.x, off);
        acc.y += __shfl_xor_sync(0xffffffffu, acc.y, off);
        acc.z += __shfl_xor_sync(0xffffffffu, acc.z, off);
        acc.w += __shfl_xor_sync(0xffffffffu, acc.w, off);
    }
    if (grp == 0) {
        float d = g_Dinv[node];
        float r = 2.0f / lam[0];
        float4 uv = ((const float4*)u)[node * 8 + sub];
        float4 x1 = ((const float4*)g_X1)[node * 8 + sub];
        float4 x2;
        x2.x = -2.0f * r * (acc.x * d) + 2.0f * (r - 1.0f) * x1.x - uv.x;
        x2.y = -2.0f * r * (acc.y * d) + 2.0f * (r - 1.0f) * x1.y - uv.y;
        x2.z = -2.0f * r * (acc.z * d) + 2.0f * (r - 1.0f) * x1.z - uv.z;
        x2.w = -2.0f * r * (acc.w * d) + 2.0f * (r - 1.0f) * x1.w - uv.w;
        ((float4*)&xsh[wid][0])[sub] = uv;
        ((float4*)&xsh[wid][32])[sub] = x1;
        ((float4*)&xsh[wid][64])[sub] = x2;
    }
    __syncwarp();

    float acc1s = sb1[lane];
    const float4* xr = (const float4*)&xsh[wid][0];
    const float4* w1 = (const float4*)&sW1t[lane * 100];
#pragma unroll
    for (int j4 = 0; j4 < 24; j4++) {
        float4 xv = xr[j4];
        float4 wv = w1[j4];
        acc1s += xv.x * wv.x + xv.y * wv.y + xv.z * wv.z + xv.w * wv.w;
    }
    float hc = fmaxf(acc1s, 0.0f);
    hcsh[wid][lane] = hc;
    __syncwarp();

    float fs = sb2[lane], fd = sb3[lane];
    const float4* hr = (const float4*)&hcsh[wid][0];
    const float4* w2 = (const float4*)&sW2t[lane * 36];
    const float4* w3 = (const float4*)&sW3t[lane * 36];
#pragma unroll
    for (int j4 = 0; j4 < 8; j4++) {
        float4 hv = hr[j4];
        float4 a2 = w2[j4];
        float4 a3 = w3[j4];
        fs += hv.x * a2.x + hv.y * a2.y + hv.z * a2.z + hv.w * a2.w;
        fd += hv.x * a3.x + hv.y * a3.y + hv.z * a3.z + hv.w * a3.w;
    }
    g_FS[node * DIM + lane] = fs;
    g_FD[node * DIM + lane] = fd;
}

// GATv2 fused edge softmax + aggregation, no max subtraction (logits bounded
// ~13 -> exp safe in fp32). Group-mask shuffles inside the divergent loop;
// full mask after reconvergence. Re-zeroes g_deg for the next call.
__global__ void k_attn(float* __restrict__ out, const float* __restrict__ attn, int n) {
    int gid = blockIdx.x * blockDim.x + threadIdx.x;
    if (gid < NN) g_deg[gid] = 0;          // restore call-entry invariant
    int w = gid >> 5;
    int lane = threadIdx.x & 31;
    if (w >= n) return;
    int grp = lane >> 3, sub = lane & 7;
    unsigned gmask = 0xffu << (grp * 8);
    int s0 = g_rowptr[w], s1 = g_rowptr[w + 1];
    const float4* FS4 = (const float4*)g_FS;
    float4 a4 = ((const float4*)attn)[sub];
    float4 fd4 = ((const float4*)g_FD)[w * 8 + sub];

    float den = 0.0f;
    float4 acc = make_float4(0.f, 0.f, 0.f, 0.f);

    for (int e = s0 + grp; e < s1; e += 4) {
        int sid = g_csrc[e];
        float4 v = FS4[sid * 8 + sub];
        float4 t;
        t.x = v.x + fd4.x; t.y = v.y + fd4.y; t.z = v.z + fd4.z; t.w = v.w + fd4.w;
        t.x = (t.x > 0.f) ? t.x : NEG_SLOPE * t.x;
        t.y = (t.y > 0.f) ? t.y : NEG_SLOPE * t.y;
        t.z = (t.z > 0.f) ? t.z : NEG_SLOPE * t.z;
        t.w = (t.w > 0.f) ? t.w : NEG_SLOPE * t.w;
        float l = t.x * a4.x + t.y * a4.y + t.z * a4.z + t.w * a4.w;
#pragma unroll
        for (int off = 1; off <= 4; off <<= 1)
            l += __shfl_xor_sync(gmask, l, off);   // group-local, converged
        float p = __expf(l);
        den += p;
        acc.x += p * v.x; acc.y += p * v.y; acc.z += p * v.z; acc.w += p * v.w;
    }

    // merge the 4 group partial sums (all lanes reconverged -> full mask ok)
#pragma unroll
    for (int off = 8; off <= 16; off <<= 1) {
        den   += __shfl_xor_sync(0xffffffffu, den, off);
        acc.x += __shfl_xor_sync(0xffffffffu, acc.x, off);
        acc.y += __shfl_xor_sync(0xffffffffu, acc.y, off);
        acc.z += __shfl_xor_sync(0xffffffffu, acc.z, off);
        acc.w += __shfl_xor_sync(0xffffffffu, acc.w, off);
    }

    if (grp == 0) {
        float4 o;
        if (den > 0.0f) {
            float inv = 1.0f / den;
            o.x = acc.x * inv; o.y = acc.y * inv; o.z = acc.z * inv; o.w = acc.w * inv;
        } else {
            o = make_float4(0.f, 0.f, 0.f, 0.f);
        }
        ((float4*)out)[w * 8 + sub] = o;
    }
}

// ---------------------------------------------------------------------
extern "C" void kernel_launch(void* const* d_in, const int* in_sizes, int n_in,
                              void* d_out, int out_size) {
    const float* u     = (const float*)d_in[0];
    const float* lam   = (const float*)d_in[1];
    const int*   esrc  = (const int*)d_in[2];
    const int*   edst  = (const int*)d_in[3];
    const float* chebW = (const float*)d_in[4];
    const float* chebb = (const float*)d_in[5];
    const float* srcW  = (const float*)d_in[6];
    const float* srcb  = (const float*)d_in[7];
    const float* dstW  = (const float*)d_in[8];
    const float* dstb  = (const float*)d_in[9];
    const float* attn  = (const float*)d_in[10];
    float* out = (float*)d_out;

    int N = in_sizes[0] / DIM;
    int E = in_sizes[2];

    int tb = 256;
    int gWarp = (N * 32 + tb - 1) / tb;
    int gNode32 = (N + 31) / 32;

    k_csr<<<CSR_BLOCKS, CSR_THREADS>>>(u, esrc, edst, N, E);  // 0
    k_aggcheb<<<gWarp, tb>>>(u, lam, N);                      // 1
    k_aggnode<<<gNode32, 1024>>>(u, lam, chebW, chebb,
                                 srcW, srcb, dstW, dstb, N);  // 2
    k_attn<<<gWarp, tb>>>(out, attn, N);                      // 3  <- ncu lands here
}

// round 14
// speedup vs baseline: 1.0449x; 1.0449x over previous
#include <cuda_runtime.h>
#include <cuda_bf16.h>
#include <float.h>

#define NN 100000
#define NE 1600000
#define DIM 32
#define NEG_SLOPE 0.2f
#define CSR_BLOCKS 148
#define CSR_THREADS 1024

// -------- static device scratch (16B aligned for float4 access) --------
// Invariant: g_deg == 0 at every kernel_launch entry (zero at module load,
// re-zeroed by k_attn each call). Barrier cnt returns to 0 after each use;
// gen increases monotonically (wrap-safe).
__device__ int      g_deg[NN];
__device__ int      g_cursor[NN];
__device__ int      g_rowptr[NN + 1];
__device__ int      g_partial[CSR_BLOCKS];
__device__ unsigned g_bar_cnt = 0;
__device__ unsigned g_bar_gen = 0;
__device__ int      g_csrc[NE];                    // src ids grouped by dst (CSR)
__device__ float    g_Dinv[NN];
__device__ __align__(16) float g_A[NN * DIM];      // pass-1 agg input (u*Dinv)
__device__ __align__(16) float g_A2[NN * DIM];     // pass-2 agg input (X1*Dinv)
__device__ __align__(16) float g_X1[NN * DIM];
__device__ __align__(16) float g_FS[NN * DIM];     // fsrc
__device__ __align__(16) float g_FD[NN * DIM];     // fdst

// Sense-reversing grid barrier. Safe: all CSR_BLOCKS co-resident
// (1 block/SM, 148 <= 152 SMs on GB300).
__device__ __forceinline__ void grid_bar() {
    __syncthreads();
    if (threadIdx.x == 0) {
        __threadfence();
        unsigned gen = *(volatile unsigned*)&g_bar_gen;
        unsigned a = atomicAdd(&g_bar_cnt, 1u);
        if (a == gridDim.x - 1) {
            *(volatile unsigned*)&g_bar_cnt = 0;
            __threadfence();
            atomicAdd(&g_bar_gen, 1u);            // release
        } else {
            while (*(volatile unsigned*)&g_bar_gen == gen) __nanosleep(64);
        }
        __threadfence();
    }
    __syncthreads();
}

// Block-wide exclusive scan over 1024 threads. Returns (exclusive, total).
__device__ __forceinline__ int2 block_scan(int v, int* swarp) {
    int lane = threadIdx.x & 31, w5 = threadIdx.x >> 5;
    int x = v;
#pragma unroll
    for (int off = 1; off < 32; off <<= 1) {
        int y = __shfl_up_sync(0xffffffffu, x, off);
        if (lane >= off) x += y;
    }
    if (lane == 31) swarp[w5] = x;
    __syncthreads();
    if (w5 == 0) {
        int s = swarp[lane];
#pragma unroll
        for (int off = 1; off < 32; off <<= 1) {
            int y = __shfl_up_sync(0xffffffffu, s, off);
            if (lane >= off) s += y;
        }
        swarp[lane] = s;
    }
    __syncthreads();
    int incl = x + (w5 > 0 ? swarp[w5 - 1] : 0);
    int total = swarp[31];
    __syncthreads();                               // protect smem reuse
    return make_int2(incl - v, total);
}

// Persistent: histogram -> scan -> rowptr/cursor/Dinv -> A = u*Dinv.
// Scatter stays a separate full-grid kernel (atomics want max TLP).
__global__ __launch_bounds__(CSR_THREADS, 1)
void k_histscan(const float* __restrict__ u, const int* __restrict__ edst,
                int n, int e) {
    __shared__ int swarp[32];
    int tid = threadIdx.x, bid = blockIdx.x;
    int gt = bid * CSR_THREADS + tid;
    int gsz = gridDim.x * CSR_THREADS;

    // ---- phase A: degree histogram ----
    for (int i = gt; i < e; i += gsz)
        atomicAdd(&g_deg[edst[i]], 1);
    grid_bar();

    // ---- phase B1: block-local scan of degrees (1 node / thread) ----
    int node = gt;
    int v = (node < n) ? g_deg[node] : 0;
    int2 sc = block_scan(v, swarp);
    if (tid == 0) g_partial[bid] = sc.y;
    grid_bar();

    // ---- phase B2: block 0 scans the 148 block totals ----
    if (bid == 0) {
        int vv = (tid < CSR_BLOCKS) ? g_partial[tid] : 0;
        int2 sc2 = block_scan(vv, swarp);
        if (tid < CSR_BLOCKS) g_partial[tid] = sc2.x;
        if (tid == CSR_BLOCKS - 1) g_rowptr[n] = sc2.x + vv;   // grand total
    }
    grid_bar();

    // ---- phase B3: write rowptr / cursor / Dinv ----
    if (node < n) {
        int off = g_partial[bid] + sc.x;
        g_rowptr[node] = off;
        g_cursor[node] = off;
        float dg = (float)v;
        g_Dinv[node] = rsqrtf(dg < 1.0f ? 1.0f : dg);
    }
    grid_bar();

    // ---- phase C: A = u * Dinv (coalesced float4, cross-block Dinv) ----
    const float4* u4 = (const float4*)u;
    float4* A4 = (float4*)g_A;
    int n8 = n * 8;
    for (int j = gt; j < n8; j += gsz) {
        float d = g_Dinv[j >> 3];
        float4 vv = u4[j];
        vv.x *= d; vv.y *= d; vv.z *= d; vv.w *= d;
        A4[j] = vv;
    }
}

// Full-grid scatter: max TLP for the 1.6M atomics + scattered stores.
__global__ void k_scatter(const int* __restrict__ esrc, const int* __restrict__ edst, int e) {
    int i = blockIdx.x * blockDim.x + threadIdx.x;
    if (i < e) {
        int p = atomicAdd(&g_cursor[edst[i]], 1);
        g_csrc[p] = esrc[i];
    }
}

// agg pass 1 fused with cheb1. Warp per node; 4 groups of 8 lanes, group =
// edge. Plain counted loop — measured fastest (R8/R12: ~33us).
__global__ void k_aggcheb(const float* __restrict__ u, const float* __restrict__ lam, int n) {
    int w = (blockIdx.x * blockDim.x + threadIdx.x) >> 5;
    int lane = threadIdx.x & 31;
    if (w >= n) return;
    int grp = lane >> 3, sub = lane & 7;
    int s0 = g_rowptr[w], s1 = g_rowptr[w + 1];
    const float4* A4 = (const float4*)g_A;
    float4 acc = make_float4(0.f, 0.f, 0.f, 0.f);
    for (int e = s0 + grp; e < s1; e += 4) {
        int sid = g_csrc[e];
        float4 v = A4[sid * 8 + sub];
        acc.x += v.x; acc.y += v.y; acc.z += v.z; acc.w += v.w;
    }
    // all lanes reconverged: full-warp shuffles safe
#pragma unroll
    for (int off = 8; off <= 16; off <<= 1) {
        acc.x += __shfl_xor_sync(0xffffffffu, acc.x, off);
        acc.y += __shfl_xor_sync(0xffffffffu, acc.y, off);
        acc.z += __shfl_xor_sync(0xffffffffu, acc.z, off);
        acc.w += __shfl_xor_sync(0xffffffffu, acc.w, off);
    }
    if (grp == 0) {
        float d = g_Dinv[w];
        float r = 2.0f / lam[0];
        float4 uv = ((const float4*)u)[w * 8 + sub];
        float4 x1;
        x1.x = -r * (acc.x * d) + (r - 1.0f) * uv.x;
        x1.y = -r * (acc.y * d) + (r - 1.0f) * uv.y;
        x1.z = -r * (acc.z * d) + (r - 1.0f) * uv.z;
        x1.w = -r * (acc.w * d) + (r - 1.0f) * uv.w;
        ((float4*)g_X1)[w * 8 + sub] = x1;
        float4 a; a.x = x1.x * d; a.y = x1.y * d; a.z = x1.z * d; a.w = x1.w * d;
        ((float4*)g_A2)[w * 8 + sub] = a;
    }
}

// agg pass 2 fused with node GEMMs. 1024-thread blocks = 32 nodes/block.
__global__ __launch_bounds__(1024, 1)
void k_aggnode(const float* __restrict__ u, const float* __restrict__ lam,
               const float* __restrict__ Wc, const float* __restrict__ bc,
               const float* __restrict__ Ws, const float* __restrict__ bs,
               const float* __restrict__ Wd, const float* __restrict__ bd,
               int n) {
    __shared__ __align__(16) float sW1t[32 * 100];
    __shared__ __align__(16) float sW2t[32 * 36];
    __shared__ __align__(16) float sW3t[32 * 36];
    __shared__ float sb1[32], sb2[32], sb3[32];
    __shared__ __align__(16) float xsh[32][96];
    __shared__ __align__(16) float hcsh[32][32];

    int tid = threadIdx.x;
    for (int i = tid; i < 96 * 32; i += 1024) {
        int j = i >> 5, d = i & 31;
        sW1t[d * 100 + j] = Wc[i];
    }
    for (int i = tid; i < 32 * 32; i += 1024) {
        int j = i >> 5, d = i & 31;
        sW2t[d * 36 + j] = Ws[i];
        sW3t[d * 36 + j] = Wd[i];
    }
    if (tid < 32) { sb1[tid] = bc[tid]; sb2[tid] = bs[tid]; sb3[tid] = bd[tid]; }
    __syncthreads();

    int wid = tid >> 5, lane = tid & 31;
    int node = blockIdx.x * 32 + wid;
    if (node >= n) return;
    int grp = lane >> 3, sub = lane & 7;

    int s0 = g_rowptr[node], s1 = g_rowptr[node + 1];
    const float4* A4 = (const float4*)g_A2;
    float4 acc = make_float4(0.f, 0.f, 0.f, 0.f);
    for (int e = s0 + grp; e < s1; e += 4) {
        int sid = g_csrc[e];
        float4 v = A4[sid * 8 + sub];
        acc.x += v.x; acc.y += v.y; acc.z += v.z; acc.w += v.w;
    }
#pragma unroll
    for (int off = 8; off <= 16; off <<= 1) {
        acc.x += __shfl_xor_sync(0xffffffffu, acc.x, off);
        acc.y += __shfl_xor_sync(0xffffffffu, acc.y, off);
        acc.z += __shfl_xor_sync(0xffffffffu, acc.z, off);
        acc.w += __shfl_xor_sync(0xffffffffu, acc.w, off);
    }
    if (grp == 0) {
        float d = g_Dinv[node];
        float r = 2.0f / lam[0];
        float4 uv = ((const float4*)u)[node * 8 + sub];
        float4 x1 = ((const float4*)g_X1)[node * 8 + sub];
        float4 x2;
        x2.x = -2.0f * r * (acc.x * d) + 2.0f * (r - 1.0f) * x1.x - uv.x;
        x2.y = -2.0f * r * (acc.y * d) + 2.0f * (r - 1.0f) * x1.y - uv.y;
        x2.z = -2.0f * r * (acc.z * d) + 2.0f * (r - 1.0f) * x1.z - uv.z;
        x2.w = -2.0f * r * (acc.w * d) + 2.0f * (r - 1.0f) * x1.w - uv.w;
        ((float4*)&xsh[wid][0])[sub] = uv;
        ((float4*)&xsh[wid][32])[sub] = x1;
        ((float4*)&xsh[wid][64])[sub] = x2;
    }
    __syncwarp();

    float acc1s = sb1[lane];
    const float4* xr = (const float4*)&xsh[wid][0];
    const float4* w1 = (const float4*)&sW1t[lane * 100];
#pragma unroll
    for (int j4 = 0; j4 < 24; j4++) {
        float4 xv = xr[j4];
        float4 wv = w1[j4];
        acc1s += xv.x * wv.x + xv.y * wv.y + xv.z * wv.z + xv.w * wv.w;
    }
    float hc = fmaxf(acc1s, 0.0f);
    hcsh[wid][lane] = hc;
    __syncwarp();

    float fs = sb2[lane], fd = sb3[lane];
    const float4* hr = (const float4*)&hcsh[wid][0];
    const float4* w2 = (const float4*)&sW2t[lane * 36];
    const float4* w3 = (const float4*)&sW3t[lane * 36];
#pragma unroll
    for (int j4 = 0; j4 < 8; j4++) {
        float4 hv = hr[j4];
        float4 a2 = w2[j4];
        float4 a3 = w3[j4];
        fs += hv.x * a2.x + hv.y * a2.y + hv.z * a2.z + hv.w * a2.w;
        fd += hv.x * a3.x + hv.y * a3.y + hv.z * a3.z + hv.w * a3.w;
    }
    g_FS[node * DIM + lane] = fs;
    g_FD[node * DIM + lane] = fd;
}

// GATv2 fused edge softmax + aggregation, no max subtraction (logits bounded
// ~13 -> exp safe in fp32). launch_bounds(256,7) caps regs at 36 (was 39) to
// lift occupancy 48->56 warps/SM with low spill risk. Group-mask shuffles in
// the divergent loop; full mask after reconvergence. Re-zeroes g_deg.
__global__ __launch_bounds__(256, 7)
void k_attn(float* __restrict__ out, const float* __restrict__ attn, int n) {
    int gid = blockIdx.x * blockDim.x + threadIdx.x;
    if (gid < NN) g_deg[gid] = 0;          // restore call-entry invariant
    int w = gid >> 5;
    int lane = threadIdx.x & 31;
    if (w >= n) return;
    int grp = lane >> 3, sub = lane & 7;
    unsigned gmask = 0xffu << (grp * 8);
    int s0 = g_rowptr[w], s1 = g_rowptr[w + 1];
    const float4* FS4 = (const float4*)g_FS;
    float4 a4 = ((const float4*)attn)[sub];
    float4 fd4 = ((const float4*)g_FD)[w * 8 + sub];

    float den = 0.0f;
    float4 acc = make_float4(0.f, 0.f, 0.f, 0.f);

    for (int e = s0 + grp; e < s1; e += 4) {
        int sid = g_csrc[e];
        float4 v = FS4[sid * 8 + sub];
        float4 t;
        t.x = v.x + fd4.x; t.y = v.y + fd4.y; t.z = v.z + fd4.z; t.w = v.w + fd4.w;
        t.x = (t.x > 0.f) ? t.x : NEG_SLOPE * t.x;
        t.y = (t.y > 0.f) ? t.y : NEG_SLOPE * t.y;
        t.z = (t.z > 0.f) ? t.z : NEG_SLOPE * t.z;
        t.w = (t.w > 0.f) ? t.w : NEG_SLOPE * t.w;
        float l = t.x * a4.x + t.y * a4.y + t.z * a4.z + t.w * a4.w;
#pragma unroll
        for (int off = 1; off <= 4; off <<= 1)
            l += __shfl_xor_sync(gmask, l, off);   // group-local, converged
        float p = __expf(l);
        den += p;
        acc.x += p * v.x; acc.y += p * v.y; acc.z += p * v.z; acc.w += p * v.w;
    }

    // merge the 4 group partial sums (all lanes reconverged -> full mask ok)
#pragma unroll
    for (int off = 8; off <= 16; off <<= 1) {
        den   += __shfl_xor_sync(0xffffffffu, den, off);
        acc.x += __shfl_xor_sync(0xffffffffu, acc.x, off);
        acc.y += __shfl_xor_sync(0xffffffffu, acc.y, off);
        acc.z += __shfl_xor_sync(0xffffffffu, acc.z, off);
        acc.w += __shfl_xor_sync(0xffffffffu, acc.w, off);
    }

    if (grp == 0) {
        float4 o;
        if (den > 0.0f) {
            float inv = 1.0f / den;
            o.x = acc.x * inv; o.y = acc.y * inv; o.z = acc.z * inv; o.w = acc.w * inv;
        } else {
            o = make_float4(0.f, 0.f, 0.f, 0.f);
        }
        ((float4*)out)[w * 8 + sub] = o;
    }
}

// ---------------------------------------------------------------------
extern "C" void kernel_launch(void* const* d_in, const int* in_sizes, int n_in,
                              void* d_out, int out_size) {
    const float* u     = (const float*)d_in[0];
    const float* lam   = (const float*)d_in[1];
    const int*   esrc  = (const int*)d_in[2];
    const int*   edst  = (const int*)d_in[3];
    const float* chebW = (const float*)d_in[4];
    const float* chebb = (const float*)d_in[5];
    const float* srcW  = (const float*)d_in[6];
    const float* srcb  = (const float*)d_in[7];
    const float* dstW  = (const float*)d_in[8];
    const float* dstb  = (const float*)d_in[9];
    const float* attn  = (const float*)d_in[10];
    float* out = (float*)d_out;

    int N = in_sizes[0] / DIM;
    int E = in_sizes[2];

    int tb = 256;
    int gE = (E + tb - 1) / tb;
    int gWarp = (N * 32 + tb - 1) / tb;
    int gNode32 = (N + 31) / 32;

    k_histscan<<<CSR_BLOCKS, CSR_THREADS>>>(u, edst, N, E);   // 0
    k_scatter<<<gE, tb>>>(esrc, edst, E);                     // 1
    k_aggcheb<<<gWarp, tb>>>(u, lam, N);                      // 2
    k_aggnode<<<gNode32, 1024>>>(u, lam, chebW, chebb,
                                 srcW, srcb, dstW, dstb, N);  // 3  <- ncu lands here
    k_attn<<<gWarp, tb>>>(out, attn, N);                      // 4
}